// round 7
// baseline (speedup 1.0000x reference)
#include <cuda_runtime.h>

// SpatialTransformer: trilinear warp of vol[0] ([160,192,224,2] f32) by dense
// shift field trf[0] ([160,192,224,3] f32). Reference semantics: loc clipped,
// loc0=clip(floor), loc1=clip(loc0+1), w_c0=loc1-loc.
//
// One block per z-row (224 threads), grid = 160*192 rows.
// R6 model: L1tex wavefront-bound; gathers dominate via per-lane (x0,y0)
// scatter. Merge the two z-corners of each (x,y) row into one aligned float4
// load (covers both when z0 even); odd-z0 lanes fetch z1 with a predicated
// half-active float2 load. 8 scattered gathers -> 4 full + 4 half.

static constexpr int D0 = 160;
static constexpr int D1 = 192;
static constexpr int D2 = 224;

__global__ __launch_bounds__(D2) void st_warp_kernel(
    const float* __restrict__ vol,   // [D0,D1,D2,2]
    const float* __restrict__ trf,   // [D0,D1,D2,3]
    float2* __restrict__ out)        // [D0,D1,D2] of float2 (2 channels)
{
    __shared__ float s_trf[D2 * 3];          // 2688 B, one row of shifts

    int row = blockIdx.x;            // 0 .. D0*D1-1
    int z = threadIdx.x;             // 0 .. 223

    // cooperative coalesced stage of this row's trf (2688 B = 168 float4)
    const float4* tr4 = (const float4*)(trf + (size_t)row * (D2 * 3));
    if (threadIdx.x < (D2 * 3) / 4)
        ((float4*)s_trf)[threadIdx.x] = tr4[threadIdx.x];
    __syncthreads();

    int y = row % D1;
    int x = row / D1;
    int i = row * D2 + z;            // flat voxel index

    float sx = s_trf[3 * z + 0];
    float sy = s_trf[3 * z + 1];
    float sz = s_trf[3 * z + 2];

    const float mx = (float)(D0 - 1);
    const float my = (float)(D1 - 1);
    const float mz = (float)(D2 - 1);

    float lx = fminf(fmaxf((float)x + sx, 0.0f), mx);
    float ly = fminf(fmaxf((float)y + sy, 0.0f), my);
    float lz = fminf(fmaxf((float)z + sz, 0.0f), mz);

    float fx0 = floorf(lx), fy0 = floorf(ly), fz0 = floorf(lz);
    float fx1 = fminf(fx0 + 1.0f, mx);
    float fy1 = fminf(fy0 + 1.0f, my);
    float fz1 = fminf(fz0 + 1.0f, mz);

    // reference weights: w_c0 = loc1 - loc, w_c1 = 1 - w_c0
    float wx0 = fx1 - lx, wx1 = 1.0f - wx0;
    float wy0 = fy1 - ly, wy1 = 1.0f - wy0;
    float wz0 = fz1 - lz, wz1 = 1.0f - wz0;

    int x0 = (int)fx0, x1 = (int)fx1;
    int y0 = (int)fy0, y1 = (int)fy1;
    int z0 = (int)fz0, z1 = (int)fz1;

    const float2* v2 = (const float2*)vol;   // [D0,D1,D2] of float2

    int bx0 = x0 * D1;
    int bx1 = x1 * D1;
    int r00 = (bx0 + y0) * D2;
    int r01 = (bx0 + y1) * D2;
    int r10 = (bx1 + y0) * D2;
    int r11 = (bx1 + y1) * D2;

    // z-pair fetch: aligned float4 at e = z0&~1 covers float2 elems (e, e+1).
    // Row starts are even (D2=224 even) and vol is 256B-aligned, so the
    // address is 16B-aligned. z0 even => both corners in one load.
    int e = z0 & ~1;
    bool odd = (z0 & 1);

    float4 p00 = __ldg((const float4*)(v2 + r00 + e));
    float4 p01 = __ldg((const float4*)(v2 + r01 + e));
    float4 p10 = __ldg((const float4*)(v2 + r10 + e));
    float4 p11 = __ldg((const float4*)(v2 + r11 + e));

    float2 a00, a01, a10, a11;       // z-lerped row values (both channels)
    if (odd) {
        // corner z0 = (p.z, p.w); corner z1 fetched separately (half-warp)
        float2 q00 = __ldg(v2 + r00 + z1);
        float2 q01 = __ldg(v2 + r01 + z1);
        float2 q10 = __ldg(v2 + r10 + z1);
        float2 q11 = __ldg(v2 + r11 + z1);
        a00.x = wz0 * p00.z + wz1 * q00.x;  a00.y = wz0 * p00.w + wz1 * q00.y;
        a01.x = wz0 * p01.z + wz1 * q01.x;  a01.y = wz0 * p01.w + wz1 * q01.y;
        a10.x = wz0 * p10.z + wz1 * q10.x;  a10.y = wz0 * p10.w + wz1 * q10.y;
        a11.x = wz0 * p11.z + wz1 * q11.x;  a11.y = wz0 * p11.w + wz1 * q11.y;
    } else {
        // corner z0 = (p.x, p.y), corner z1 = (p.z, p.w)  [z1 = z0+1 always
        // when z0 even, since z0 <= 222]
        a00.x = wz0 * p00.x + wz1 * p00.z;  a00.y = wz0 * p00.y + wz1 * p00.w;
        a01.x = wz0 * p01.x + wz1 * p01.z;  a01.y = wz0 * p01.y + wz1 * p01.w;
        a10.x = wz0 * p10.x + wz1 * p10.z;  a10.y = wz0 * p10.y + wz1 * p10.w;
        a11.x = wz0 * p11.x + wz1 * p11.z;  a11.y = wz0 * p11.y + wz1 * p11.w;
    }

    // y then x lerp
    float b0x = wy0 * a00.x + wy1 * a01.x;
    float b0y = wy0 * a00.y + wy1 * a01.y;
    float b1x = wy0 * a10.x + wy1 * a11.x;
    float b1y = wy0 * a10.y + wy1 * a11.y;

    float2 o;
    o.x = wx0 * b0x + wx1 * b1x;
    o.y = wx0 * b0y + wx1 * b1y;
    out[i] = o;
}

extern "C" void kernel_launch(void* const* d_in, const int* in_sizes, int n_in,
                              void* d_out, int out_size)
{
    const float* vol = (const float*)d_in[0];   // [2,160,192,224,2]; batch 0 at base
    const float* trf = (const float*)d_in[1];   // [2,160,192,224,3]; batch 0 at base
    float2* out = (float2*)d_out;               // [160,192,224,2]

    st_warp_kernel<<<D0 * D1, D2>>>(vol, trf, out);
}